// round 1
// baseline (speedup 1.0000x reference)
#include <cuda_runtime.h>
#include <math.h>

#define NEG_INF (-1e30f)
#define NB 16
#define LC 2048
#define LQ 512
#define DD 512
#define D4 2048

// Scratch (device globals; no allocations allowed)
__device__ float g_Cp[NB * LC * DD];   // compacted leaky_relu(C@W1^T+b1)  64MB
__device__ float g_Qp[NB * LQ * DD];   // leaky_relu(Q@W1^T+b1)            16MB
__device__ float g_S [NB * LC * LQ];   // compacted S / softmax(S)         64MB
__device__ float g_A [NB * LC * DD];   // compacted attn_C                 64MB
__device__ int   g_idx[NB * LC];       // per-batch unmasked row indices
__device__ int   g_cnt[NB];            // per-batch unmasked row count

// ---------------------------------------------------------------------------
// Compaction: per batch, list of c where Cmask[b,c] != 0 (deterministic scan)
// ---------------------------------------------------------------------------
__global__ void compact_kernel(const int* __restrict__ Cmask) {
    __shared__ int toff[257];
    int b = blockIdx.x;
    int t = threadIdx.x;
    int flags[8];
    int s = 0;
#pragma unroll
    for (int i = 0; i < 8; i++) {
        flags[i] = (Cmask[b * LC + t * 8 + i] != 0) ? 1 : 0;
        s += flags[i];
    }
    toff[t + 1] = s;
    __syncthreads();
    if (t == 0) {
        toff[0] = 0;
        for (int i = 1; i <= 256; i++) toff[i] += toff[i - 1];
        g_cnt[b] = toff[256];
    }
    __syncthreads();
    int pos = toff[t];
#pragma unroll
    for (int i = 0; i < 8; i++) {
        if (flags[i]) g_idx[b * LC + (pos++)] = t * 8 + i;
    }
}

// ---------------------------------------------------------------------------
// Fill masked output rows with NEG_INF
// ---------------------------------------------------------------------------
__global__ void fill_masked_kernel(const int* __restrict__ Cmask,
                                   float* __restrict__ out) {
    int c = blockIdx.y;
    int b = blockIdx.z;
    if (Cmask[b * LC + c] != 0) return;
    float4* p = (float4*)(out + ((size_t)(b * LC + c)) * D4);
    float4 v = make_float4(NEG_INF, NEG_INF, NEG_INF, NEG_INF);
    int t = threadIdx.x;
    p[t] = v; p[t + 128] = v; p[t + 256] = v; p[t + 384] = v;
}

// ---------------------------------------------------------------------------
// GEMM 1: Y = leaky_relu(X @ W^T + bias). NT layout.
// isC=1: X=C with row compaction, Y=g_Cp. isC=0: X=Q full, Y=g_Qp.
// BM=128 BN=64 BK=16, 256 threads, 8x4 microtile.
// ---------------------------------------------------------------------------
__global__ __launch_bounds__(256, 2)
void gemm_lin_kernel(const float* __restrict__ X, const float* __restrict__ W,
                     const float* __restrict__ bias, int Lx, int isC) {
    int b  = blockIdx.z;
    int m0 = blockIdx.y * 128;
    int n0 = blockIdx.x * 64;
    int M  = isC ? g_cnt[b] : Lx;
    if (m0 >= M) return;
    float* __restrict__ Y = isC ? g_Cp : g_Qp;

    __shared__ __align__(16) float As[16][132];
    __shared__ __align__(16) float Bs[16][68];

    int tid = threadIdx.x;
    int tx = tid & 15, ty = tid >> 4;
    int lr = tid >> 2;
    int kq = (tid & 3) << 2;

    int j0 = min(m0 + lr, M - 1);
    int j1 = min(m0 + lr + 64, M - 1);
    int s0 = isC ? g_idx[b * LC + j0] : j0;
    int s1 = isC ? g_idx[b * LC + j1] : j1;
    const float* Ap0 = X + ((size_t)b * Lx + s0) * DD + kq;
    const float* Ap1 = X + ((size_t)b * Lx + s1) * DD + kq;
    const float* Bp  = W + (size_t)(n0 + lr) * DD + kq;

    float acc[8][4];
#pragma unroll
    for (int i = 0; i < 8; i++)
#pragma unroll
        for (int j = 0; j < 4; j++) acc[i][j] = 0.f;

    for (int k0 = 0; k0 < DD; k0 += 16) {
        float4 v0 = *(const float4*)(Ap0 + k0);
        float4 v1 = *(const float4*)(Ap1 + k0);
        float4 w0 = *(const float4*)(Bp + k0);
        As[kq + 0][lr] = v0.x; As[kq + 1][lr] = v0.y;
        As[kq + 2][lr] = v0.z; As[kq + 3][lr] = v0.w;
        As[kq + 0][lr + 64] = v1.x; As[kq + 1][lr + 64] = v1.y;
        As[kq + 2][lr + 64] = v1.z; As[kq + 3][lr + 64] = v1.w;
        Bs[kq + 0][lr] = w0.x; Bs[kq + 1][lr] = w0.y;
        Bs[kq + 2][lr] = w0.z; Bs[kq + 3][lr] = w0.w;
        __syncthreads();
#pragma unroll
        for (int kk = 0; kk < 16; kk++) {
            float4 a0 = *(const float4*)&As[kk][ty * 8];
            float4 a1 = *(const float4*)&As[kk][ty * 8 + 4];
            float4 bv = *(const float4*)&Bs[kk][tx * 4];
            float a[8] = {a0.x, a0.y, a0.z, a0.w, a1.x, a1.y, a1.z, a1.w};
            float bb[4] = {bv.x, bv.y, bv.z, bv.w};
#pragma unroll
            for (int i = 0; i < 8; i++)
#pragma unroll
                for (int j = 0; j < 4; j++)
                    acc[i][j] = fmaf(a[i], bb[j], acc[i][j]);
        }
        __syncthreads();
    }
#pragma unroll
    for (int i = 0; i < 8; i++) {
        int m = m0 + ty * 8 + i;
        if (m < M) {
            float* yr = Y + ((size_t)b * Lx + m) * DD;
#pragma unroll
            for (int j = 0; j < 4; j++) {
                int n = n0 + tx * 4 + j;
                float y = acc[i][j] + bias[n];
                yr[n] = (y > 0.f) ? y : 0.01f * y;
            }
        }
    }
}

// ---------------------------------------------------------------------------
// GEMM 2: S[b,j,q] = sum_d Cp[b,j,d] * Qp[b,q,d]  (NT, compacted rows)
// ---------------------------------------------------------------------------
__global__ __launch_bounds__(256, 2)
void gemm_s_kernel() {
    int b  = blockIdx.z;
    int m0 = blockIdx.y * 128;
    int n0 = blockIdx.x * 64;
    int M  = g_cnt[b];
    if (m0 >= M) return;

    __shared__ __align__(16) float As[16][132];
    __shared__ __align__(16) float Bs[16][68];

    int tid = threadIdx.x;
    int tx = tid & 15, ty = tid >> 4;
    int lr = tid >> 2;
    int kq = (tid & 3) << 2;

    int j0 = min(m0 + lr, M - 1);
    int j1 = min(m0 + lr + 64, M - 1);
    const float* Ap0 = g_Cp + ((size_t)b * LC + j0) * DD + kq;
    const float* Ap1 = g_Cp + ((size_t)b * LC + j1) * DD + kq;
    const float* Bp  = g_Qp + ((size_t)b * LQ + n0 + lr) * DD + kq;

    float acc[8][4];
#pragma unroll
    for (int i = 0; i < 8; i++)
#pragma unroll
        for (int j = 0; j < 4; j++) acc[i][j] = 0.f;

    for (int k0 = 0; k0 < DD; k0 += 16) {
        float4 v0 = *(const float4*)(Ap0 + k0);
        float4 v1 = *(const float4*)(Ap1 + k0);
        float4 w0 = *(const float4*)(Bp + k0);
        As[kq + 0][lr] = v0.x; As[kq + 1][lr] = v0.y;
        As[kq + 2][lr] = v0.z; As[kq + 3][lr] = v0.w;
        As[kq + 0][lr + 64] = v1.x; As[kq + 1][lr + 64] = v1.y;
        As[kq + 2][lr + 64] = v1.z; As[kq + 3][lr + 64] = v1.w;
        Bs[kq + 0][lr] = w0.x; Bs[kq + 1][lr] = w0.y;
        Bs[kq + 2][lr] = w0.z; Bs[kq + 3][lr] = w0.w;
        __syncthreads();
#pragma unroll
        for (int kk = 0; kk < 16; kk++) {
            float4 a0 = *(const float4*)&As[kk][ty * 8];
            float4 a1 = *(const float4*)&As[kk][ty * 8 + 4];
            float4 bv = *(const float4*)&Bs[kk][tx * 4];
            float a[8] = {a0.x, a0.y, a0.z, a0.w, a1.x, a1.y, a1.z, a1.w};
            float bb[4] = {bv.x, bv.y, bv.z, bv.w};
#pragma unroll
            for (int i = 0; i < 8; i++)
#pragma unroll
                for (int j = 0; j < 4; j++)
                    acc[i][j] = fmaf(a[i], bb[j], acc[i][j]);
        }
        __syncthreads();
    }
#pragma unroll
    for (int i = 0; i < 8; i++) {
        int m = m0 + ty * 8 + i;
        if (m < M) {
            float* yr = g_S + ((size_t)b * LC + m) * LQ;
#pragma unroll
            for (int j = 0; j < 4; j++) yr[n0 + tx * 4 + j] = acc[i][j];
        }
    }
}

// ---------------------------------------------------------------------------
// Softmax over q (512) with Qmask, in place on g_S (compacted rows only)
// ---------------------------------------------------------------------------
__global__ void softmax_kernel(const int* __restrict__ Qmask) {
    int b = blockIdx.y, j = blockIdx.x;
    if (j >= g_cnt[b]) return;
    float* row = g_S + ((size_t)b * LC + j) * LQ;
    int t = threadIdx.x;
    int lane = t & 31, warp = t >> 5;
    float v0 = row[t];
    float v1 = row[t + 256];
    if (Qmask[b * LQ + t] == 0) v0 = NEG_INF;
    if (Qmask[b * LQ + t + 256] == 0) v1 = NEG_INF;

    __shared__ float red[8];
    __shared__ float bcast;

    float m = fmaxf(v0, v1);
#pragma unroll
    for (int o = 16; o; o >>= 1) m = fmaxf(m, __shfl_xor_sync(0xffffffffu, m, o));
    if (lane == 0) red[warp] = m;
    __syncthreads();
    if (t < 32) {
        float x = (t < 8) ? red[t] : -3.4e38f;
#pragma unroll
        for (int o = 4; o; o >>= 1) x = fmaxf(x, __shfl_xor_sync(0xffffffffu, x, o));
        if (t == 0) bcast = x;
    }
    __syncthreads();
    m = bcast;
    float e0 = expf(v0 - m), e1 = expf(v1 - m);
    float s = e0 + e1;
#pragma unroll
    for (int o = 16; o; o >>= 1) s += __shfl_xor_sync(0xffffffffu, s, o);
    __syncthreads();
    if (lane == 0) red[warp] = s;
    __syncthreads();
    if (t < 32) {
        float x = (t < 8) ? red[t] : 0.f;
#pragma unroll
        for (int o = 4; o; o >>= 1) x += __shfl_xor_sync(0xffffffffu, x, o);
        if (t == 0) bcast = x;
    }
    __syncthreads();
    float inv = 1.0f / bcast;
    row[t] = e0 * inv;
    row[t + 256] = e1 * inv;
}

// ---------------------------------------------------------------------------
// GEMM 3: A[b,j,d] = sum_q S[b,j,q] * Q[b,q,d]   (NN layout)
// ---------------------------------------------------------------------------
__global__ __launch_bounds__(256, 2)
void gemm_a_kernel(const float* __restrict__ Q) {
    int b  = blockIdx.z;
    int m0 = blockIdx.y * 128;
    int n0 = blockIdx.x * 64;
    int M  = g_cnt[b];
    if (m0 >= M) return;

    __shared__ __align__(16) float As[16][132];
    __shared__ __align__(16) float Bs[16][68];

    int tid = threadIdx.x;
    int tx = tid & 15, ty = tid >> 4;
    int lr = tid >> 2;
    int kq = (tid & 3) << 2;
    int kr = tid >> 4;            // 0..15  B-tile row (k)
    int nq = (tid & 15) << 2;     // 0..60  B-tile col quad

    int j0 = min(m0 + lr, M - 1);
    int j1 = min(m0 + lr + 64, M - 1);
    const float* Ap0 = g_S + ((size_t)b * LC + j0) * LQ + kq;
    const float* Ap1 = g_S + ((size_t)b * LC + j1) * LQ + kq;
    const float* Bp  = Q + ((size_t)b * LQ + kr) * DD + n0 + nq;

    float acc[8][4];
#pragma unroll
    for (int i = 0; i < 8; i++)
#pragma unroll
        for (int j = 0; j < 4; j++) acc[i][j] = 0.f;

    for (int k0 = 0; k0 < LQ; k0 += 16) {
        float4 v0 = *(const float4*)(Ap0 + k0);
        float4 v1 = *(const float4*)(Ap1 + k0);
        float4 w0 = *(const float4*)(Bp + (size_t)k0 * DD);
        As[kq + 0][lr] = v0.x; As[kq + 1][lr] = v0.y;
        As[kq + 2][lr] = v0.z; As[kq + 3][lr] = v0.w;
        As[kq + 0][lr + 64] = v1.x; As[kq + 1][lr + 64] = v1.y;
        As[kq + 2][lr + 64] = v1.z; As[kq + 3][lr + 64] = v1.w;
        *(float4*)&Bs[kr][nq] = w0;
        __syncthreads();
#pragma unroll
        for (int kk = 0; kk < 16; kk++) {
            float4 a0 = *(const float4*)&As[kk][ty * 8];
            float4 a1 = *(const float4*)&As[kk][ty * 8 + 4];
            float4 bv = *(const float4*)&Bs[kk][tx * 4];
            float a[8] = {a0.x, a0.y, a0.z, a0.w, a1.x, a1.y, a1.z, a1.w};
            float bb[4] = {bv.x, bv.y, bv.z, bv.w};
#pragma unroll
            for (int i = 0; i < 8; i++)
#pragma unroll
                for (int j = 0; j < 4; j++)
                    acc[i][j] = fmaf(a[i], bb[j], acc[i][j]);
        }
        __syncthreads();
    }
#pragma unroll
    for (int i = 0; i < 8; i++) {
        int m = m0 + ty * 8 + i;
        if (m < M) {
            float* yr = g_A + ((size_t)b * LC + m) * DD;
#pragma unroll
            for (int j = 0; j < 4; j++) yr[n0 + tx * 4 + j] = acc[i][j];
        }
    }
}

// ---------------------------------------------------------------------------
// Final fused kernel: cat built on the fly; dual GEMM (Wf, Wg); epilogue
// tanh/sigmoid/blend; writes unmasked output rows.
// ---------------------------------------------------------------------------
__device__ __forceinline__ float4 cat4(float4 cv, float4 av, int seg) {
    float4 x;
    if (seg == 0)      x = cv;
    else if (seg == 1) x = av;
    else if (seg == 2) { x.x = av.x - cv.x; x.y = av.y - cv.y; x.z = av.z - cv.z; x.w = av.w - cv.w; }
    else               { x.x = av.x * cv.x; x.y = av.y * cv.y; x.z = av.z * cv.z; x.w = av.w * cv.w; }
    return x;
}

__global__ __launch_bounds__(256, 2)
void final_kernel(const float* __restrict__ C, const float* __restrict__ Wf,
                  const float* __restrict__ bfv, const float* __restrict__ Wg,
                  const float* __restrict__ bgv, float* __restrict__ out) {
    int b  = blockIdx.z;
    int m0 = blockIdx.y * 128;
    int n0 = blockIdx.x * 64;
    int M  = g_cnt[b];
    if (m0 >= M) return;

    __shared__ __align__(16) float As[16][132];
    __shared__ __align__(16) float Bf[16][68];
    __shared__ __align__(16) float Bg[16][68];

    int tid = threadIdx.x;
    int tx = tid & 15, ty = tid >> 4;
    int lr = tid >> 2;
    int kq = (tid & 3) << 2;

    int j0 = min(m0 + lr, M - 1);
    int j1 = min(m0 + lr + 64, M - 1);
    int c0 = g_idx[b * LC + j0];
    int c1 = g_idx[b * LC + j1];
    const float* Cp0 = C   + ((size_t)b * LC + c0) * DD + kq;
    const float* Cp1 = C   + ((size_t)b * LC + c1) * DD + kq;
    const float* Ap0 = g_A + ((size_t)b * LC + j0) * DD + kq;
    const float* Ap1 = g_A + ((size_t)b * LC + j1) * DD + kq;
    const float* Bfp = Wf + (size_t)(n0 + lr) * D4 + kq;
    const float* Bgp = Wg + (size_t)(n0 + lr) * D4 + kq;

    float accf[8][4], accg[8][4];
#pragma unroll
    for (int i = 0; i < 8; i++)
#pragma unroll
        for (int j = 0; j < 4; j++) { accf[i][j] = 0.f; accg[i][j] = 0.f; }

    for (int k0 = 0; k0 < D4; k0 += 16) {
        int seg = k0 >> 9;
        int kk0 = k0 & 511;
        float4 cv0 = *(const float4*)(Cp0 + kk0);
        float4 av0 = *(const float4*)(Ap0 + kk0);
        float4 cv1 = *(const float4*)(Cp1 + kk0);
        float4 av1 = *(const float4*)(Ap1 + kk0);
        float4 x0 = cat4(cv0, av0, seg);
        float4 x1 = cat4(cv1, av1, seg);
        float4 wf = *(const float4*)(Bfp + k0);
        float4 wg = *(const float4*)(Bgp + k0);
        As[kq + 0][lr] = x0.x; As[kq + 1][lr] = x0.y;
        As[kq + 2][lr] = x0.z; As[kq + 3][lr] = x0.w;
        As[kq + 0][lr + 64] = x1.x; As[kq + 1][lr + 64] = x1.y;
        As[kq + 2][lr + 64] = x1.z; As[kq + 3][lr + 64] = x1.w;
        Bf[kq + 0][lr] = wf.x; Bf[kq + 1][lr] = wf.y;
        Bf[kq + 2][lr] = wf.z; Bf[kq + 3][lr] = wf.w;
        Bg[kq + 0][lr] = wg.x; Bg[kq + 1][lr] = wg.y;
        Bg[kq + 2][lr] = wg.z; Bg[kq + 3][lr] = wg.w;
        __syncthreads();
#pragma unroll
        for (int kk = 0; kk < 16; kk++) {
            float4 a0 = *(const float4*)&As[kk][ty * 8];
            float4 a1 = *(const float4*)&As[kk][ty * 8 + 4];
            float4 f4 = *(const float4*)&Bf[kk][tx * 4];
            float4 g4 = *(const float4*)&Bg[kk][tx * 4];
            float a[8] = {a0.x, a0.y, a0.z, a0.w, a1.x, a1.y, a1.z, a1.w};
            float fb[4] = {f4.x, f4.y, f4.z, f4.w};
            float gb[4] = {g4.x, g4.y, g4.z, g4.w};
#pragma unroll
            for (int i = 0; i < 8; i++) {
#pragma unroll
                for (int j = 0; j < 4; j++) {
                    accf[i][j] = fmaf(a[i], fb[j], accf[i][j]);
                    accg[i][j] = fmaf(a[i], gb[j], accg[i][j]);
                }
            }
        }
        __syncthreads();
    }

    int segn = n0 >> 9;  // uniform for the whole block (BN=64 within 512-seg)
#pragma unroll
    for (int i = 0; i < 8; i++) {
        int j = m0 + ty * 8 + i;
        if (j < M) {
            int c = g_idx[b * LC + j];
            const float* crow = C   + ((size_t)b * LC + c) * DD;
            const float* arow = g_A + ((size_t)b * LC + j) * DD;
            float* orow = out + ((size_t)b * LC + c) * (size_t)D4;
#pragma unroll
            for (int jc = 0; jc < 4; jc++) {
                int n = n0 + tx * 4 + jc;
                int nn = n & 511;
                float cval = crow[nn];
                float aval = arow[nn];
                float catv = (segn == 0) ? cval
                           : (segn == 1) ? aval
                           : (segn == 2) ? (aval - cval)
                                         : (aval * cval);
                float fv = tanhf(accf[i][jc] + bfv[n]);
                float gin = accg[i][jc] + bgv[n];
                float gv = 1.0f / (1.0f + expf(-gin));
                orow[n] = gv * fv + (1.0f - gv) * catv;
            }
        }
    }
}

// ---------------------------------------------------------------------------
extern "C" void kernel_launch(void* const* d_in, const int* in_sizes, int n_in,
                              void* d_out, int out_size) {
    const float* C     = (const float*)d_in[0];
    const float* Q     = (const float*)d_in[1];
    const int*   Cmask = (const int*)d_in[2];
    const int*   Qmask = (const int*)d_in[3];
    const float* W1    = (const float*)d_in[4];
    const float* b1    = (const float*)d_in[5];
    const float* Wf    = (const float*)d_in[6];
    const float* bfv   = (const float*)d_in[7];
    const float* Wg    = (const float*)d_in[8];
    const float* bgv   = (const float*)d_in[9];
    float* out = (float*)d_out;

    compact_kernel<<<NB, 256>>>(Cmask);
    fill_masked_kernel<<<dim3(1, LC, NB), 128>>>(Cmask, out);

    // C_ = lrelu(C@W1^T+b1), compacted rows
    gemm_lin_kernel<<<dim3(DD / 64, LC / 128, NB), 256>>>(C, W1, b1, LC, 1);
    // Q_ = lrelu(Q@W1^T+b1), all rows
    gemm_lin_kernel<<<dim3(DD / 64, LQ / 128, NB), 256>>>(Q, W1, b1, LQ, 0);
    // S = C_ @ Q_^T (compacted c)
    gemm_s_kernel<<<dim3(LQ / 64, LC / 128, NB), 256>>>();
    // masked softmax over q
    softmax_kernel<<<dim3(LC, NB), 256>>>(Qmask);
    // attn_C = S_ @ Q (compacted c)
    gemm_a_kernel<<<dim3(DD / 64, LC / 128, NB), 256>>>(Q);
    // out = gate*tanh(cat@Wf^T+bf) + (1-gate)*cat  (compacted c rows)
    final_kernel<<<dim3(D4 / 64, LC / 128, NB), 256>>>(C, Wf, bfv, Wg, bgv, out);
}

// round 2
// speedup vs baseline: 1.8966x; 1.8966x over previous
#include <cuda_runtime.h>
#include <cuda_bf16.h>
#include <math.h>

#define NEG_INF (-1e30f)
#define NB 16
#define LC 2048
#define LQ 512
#define DD 512
#define D4 2048

__device__ float g_Cp[NB * LC * DD];
__device__ float g_Qp[NB * LQ * DD];
__device__ float g_S [NB * LC * LQ];
__device__ float g_A [NB * LC * DD];
__device__ float g_Qt[NB * DD * LQ];
__device__ int   g_idx[NB * LC];
__device__ int   g_cnt[NB];

__device__ __forceinline__ unsigned pk(float a, float b) {
    __nv_bfloat162 h = __floats2bfloat162_rn(a, b);
    return *reinterpret_cast<unsigned*>(&h);
}

__device__ __forceinline__ void mma_bf16(float* d, const unsigned* a, const unsigned* b) {
    asm volatile(
        "mma.sync.aligned.m16n8k16.row.col.f32.bf16.bf16.f32 "
        "{%0,%1,%2,%3}, {%4,%5,%6,%7}, {%8,%9}, {%0,%1,%2,%3};\n"
        : "+f"(d[0]), "+f"(d[1]), "+f"(d[2]), "+f"(d[3])
        : "r"(a[0]), "r"(a[1]), "r"(a[2]), "r"(a[3]), "r"(b[0]), "r"(b[1]));
}

__device__ __forceinline__ void loadA16(unsigned* ra, const float* p) {
    float4 f0 = *(const float4*)(p);
    float4 f1 = *(const float4*)(p + 4);
    float4 f2 = *(const float4*)(p + 8);
    float4 f3 = *(const float4*)(p + 12);
    ra[0] = pk(f0.x, f0.y); ra[1] = pk(f0.z, f0.w);
    ra[2] = pk(f1.x, f1.y); ra[3] = pk(f1.z, f1.w);
    ra[4] = pk(f2.x, f2.y); ra[5] = pk(f2.z, f2.w);
    ra[6] = pk(f3.x, f3.y); ra[7] = pk(f3.z, f3.w);
}

__device__ __forceinline__ void loadB8(unsigned* rb, const float* p) {
    float4 g0 = *(const float4*)(p);
    float4 g1 = *(const float4*)(p + 4);
    rb[0] = pk(g0.x, g0.y); rb[1] = pk(g0.z, g0.w);
    rb[2] = pk(g1.x, g1.y); rb[3] = pk(g1.z, g1.w);
}

__device__ __forceinline__ void stsA(unsigned* sA, int am, int aks, const unsigned* ra) {
    int mtile = am >> 4, m15 = am & 15;
    unsigned* p = sA + ((mtile * 2 + aks) * 32 + ((m15 & 7) << 2)) * 4 + (m15 >> 3);
    p[0]  = ra[0]; p[4]  = ra[1]; p[8]  = ra[2]; p[12] = ra[3];
    p[2]  = ra[4]; p[6]  = ra[5]; p[10] = ra[6]; p[14] = ra[7];
}

__device__ __forceinline__ void stsB(unsigned* sB, int bn, int bkc, const unsigned* rb) {
    int ntile = bn >> 3, n7 = bn & 7, ksl = bkc >> 1, h = bkc & 1;
    unsigned* q = sB + ((ntile * 2 + ksl) * 32 + (n7 << 2)) * 2 + h;
    q[0] = rb[0]; q[2] = rb[1]; q[4] = rb[2]; q[6] = rb[3];
}

__global__ void compact_kernel(const int* __restrict__ Cmask) {
    __shared__ int toff[257];
    int b = blockIdx.x;
    int t = threadIdx.x;
    int flags[8];
    int s = 0;
#pragma unroll
    for (int i = 0; i < 8; i++) {
        flags[i] = (Cmask[b * LC + t * 8 + i] != 0) ? 1 : 0;
        s += flags[i];
    }
    toff[t + 1] = s;
    __syncthreads();
    if (t == 0) {
        toff[0] = 0;
        for (int i = 1; i <= 256; i++) toff[i] += toff[i - 1];
        g_cnt[b] = toff[256];
    }
    __syncthreads();
    int pos = toff[t];
#pragma unroll
    for (int i = 0; i < 8; i++) {
        if (flags[i]) g_idx[b * LC + (pos++)] = t * 8 + i;
    }
}

__global__ void fill_masked_kernel(const int* __restrict__ Cmask,
                                   float* __restrict__ out) {
    int c = blockIdx.y;
    int b = blockIdx.z;
    if (Cmask[b * LC + c] != 0) return;
    float4* p = (float4*)(out + ((size_t)(b * LC + c)) * D4);
    float4 v = make_float4(NEG_INF, NEG_INF, NEG_INF, NEG_INF);
    int t = threadIdx.x;
    p[t] = v; p[t + 128] = v; p[t + 256] = v; p[t + 384] = v;
}

__global__ void transpose_q_kernel(const float* __restrict__ Q) {
    __shared__ float t[32][33];
    int b = blockIdx.z;
    int d0 = blockIdx.x * 32, q0 = blockIdx.y * 32;
    int tx = threadIdx.x, ty = threadIdx.y;
#pragma unroll
    for (int i = 0; i < 4; i++)
        t[ty + i * 8][tx] = Q[((size_t)b * LQ + q0 + ty + i * 8) * DD + d0 + tx];
    __syncthreads();
#pragma unroll
    for (int i = 0; i < 4; i++)
        g_Qt[((size_t)b * DD + d0 + ty + i * 8) * LQ + q0 + tx] = t[tx][ty + i * 8];
}

// Generic NT bf16-MMA GEMM. B batched via Brows_per_b (0 => shared weights).
// gather: A rows via g_idx. use_cnt: M = g_cnt[b]. mode 0: bias+leakyrelu.
__global__ __launch_bounds__(256, 2)
void gemm_nt_mma(const float* __restrict__ A, int lda, int Arows_per_b,
                 const float* __restrict__ B, int ldb, int Brows_per_b,
                 float* __restrict__ Y, int ldy,
                 const float* __restrict__ bias,
                 int K, int Mfull, int use_cnt, int gather, int mode) {
    int b  = blockIdx.z;
    int m0 = blockIdx.y * 128;
    int n0 = blockIdx.x * 64;
    int M  = use_cnt ? g_cnt[b] : Mfull;
    if (m0 >= M) return;

    __shared__ __align__(16) unsigned sA[2][2048];
    __shared__ __align__(16) unsigned sB[2][1024];

    int tid = threadIdx.x;
    int am = tid >> 1, aks = tid & 1;
    int bn = tid >> 2, bkc = tid & 3;
    int j = min(m0 + am, M - 1);
    int s = gather ? g_idx[b * LC + j] : j;
    const float* Arow = A + ((size_t)b * Arows_per_b + s) * lda + aks * 16;
    const float* Brow = B + ((size_t)b * Brows_per_b + n0 + bn) * ldb + bkc * 8;

    int lane = tid & 31, w = tid >> 5;
    int wm = w >> 1, wn = w & 1;

    float acc[2][4][4];
#pragma unroll
    for (int mi = 0; mi < 2; mi++)
#pragma unroll
        for (int ni = 0; ni < 4; ni++)
#pragma unroll
            for (int r = 0; r < 4; r++) acc[mi][ni][r] = 0.f;

    unsigned ra[8], rb[4];
    loadA16(ra, Arow);
    loadB8(rb, Brow);

    const int KIT = K / 32;
    for (int it = 0; it < KIT; it++) {
        int buf = it & 1;
        stsA(sA[buf], am, aks, ra);
        stsB(sB[buf], bn, bkc, rb);
        __syncthreads();
        if (it + 1 < KIT) {
            loadA16(ra, Arow + (it + 1) * 32);
            loadB8(rb, Brow + (it + 1) * 32);
        }
#pragma unroll
        for (int ks = 0; ks < 2; ks++) {
            uint4 av[2];
            uint2 bv[4];
#pragma unroll
            for (int mi = 0; mi < 2; mi++)
                av[mi] = *(const uint4*)&sA[buf][(((wm * 2 + mi) * 2 + ks) * 32 + lane) * 4];
#pragma unroll
            for (int ni = 0; ni < 4; ni++)
                bv[ni] = *(const uint2*)&sB[buf][(((wn * 4 + ni) * 2 + ks) * 32 + lane) * 2];
#pragma unroll
            for (int mi = 0; mi < 2; mi++)
#pragma unroll
                for (int ni = 0; ni < 4; ni++)
                    mma_bf16(acc[mi][ni], (const unsigned*)&av[mi], (const unsigned*)&bv[ni]);
        }
    }

    int gid = lane >> 2, tig = lane & 3;
#pragma unroll
    for (int mi = 0; mi < 2; mi++) {
#pragma unroll
        for (int rr = 0; rr < 2; rr++) {
            int m = m0 + wm * 32 + mi * 16 + gid + rr * 8;
            if (m < M) {
                float* yr = Y + ((size_t)b * Arows_per_b + m) * ldy;
#pragma unroll
                for (int ni = 0; ni < 4; ni++) {
                    int n = n0 + wn * 32 + ni * 8 + tig * 2;
                    float v0 = acc[mi][ni][rr * 2 + 0];
                    float v1 = acc[mi][ni][rr * 2 + 1];
                    if (mode == 0) {
                        v0 += bias[n];     v1 += bias[n + 1];
                        v0 = (v0 > 0.f) ? v0 : 0.01f * v0;
                        v1 = (v1 > 0.f) ? v1 : 0.01f * v1;
                    }
                    yr[n] = v0;
                    yr[n + 1] = v1;
                }
            }
        }
    }
}

__global__ void softmax_kernel(const int* __restrict__ Qmask) {
    int b = blockIdx.y, j = blockIdx.x;
    if (j >= g_cnt[b]) return;
    float* row = g_S + ((size_t)b * LC + j) * LQ;
    int t = threadIdx.x;
    int lane = t & 31, warp = t >> 5;
    float v0 = row[t];
    float v1 = row[t + 256];
    if (Qmask[b * LQ + t] == 0) v0 = NEG_INF;
    if (Qmask[b * LQ + t + 256] == 0) v1 = NEG_INF;

    __shared__ float red[8];
    __shared__ float bcast;

    float m = fmaxf(v0, v1);
#pragma unroll
    for (int o = 16; o; o >>= 1) m = fmaxf(m, __shfl_xor_sync(0xffffffffu, m, o));
    if (lane == 0) red[warp] = m;
    __syncthreads();
    if (t < 32) {
        float x = (t < 8) ? red[t] : -3.4e38f;
#pragma unroll
        for (int o = 4; o; o >>= 1) x = fmaxf(x, __shfl_xor_sync(0xffffffffu, x, o));
        if (t == 0) bcast = x;
    }
    __syncthreads();
    m = bcast;
    float e0 = expf(v0 - m), e1 = expf(v1 - m);
    float sum = e0 + e1;
#pragma unroll
    for (int o = 16; o; o >>= 1) sum += __shfl_xor_sync(0xffffffffu, sum, o);
    __syncthreads();
    if (lane == 0) red[warp] = sum;
    __syncthreads();
    if (t < 32) {
        float x = (t < 8) ? red[t] : 0.f;
#pragma unroll
        for (int o = 4; o; o >>= 1) x += __shfl_xor_sync(0xffffffffu, x, o);
        if (t == 0) bcast = x;
    }
    __syncthreads();
    float inv = 1.0f / bcast;
    row[t] = e0 * inv;
    row[t + 256] = e1 * inv;
}

__global__ __launch_bounds__(256, 1)
void final_mma(const float* __restrict__ C, const float* __restrict__ Wf,
               const float* __restrict__ bfv, const float* __restrict__ Wg,
               const float* __restrict__ bgv, float* __restrict__ out) {
    int b  = blockIdx.z;
    int m0 = blockIdx.y * 128;
    int n0 = blockIdx.x * 64;
    int M  = g_cnt[b];
    if (m0 >= M) return;

    __shared__ __align__(16) unsigned sA[2][2048];
    __shared__ __align__(16) unsigned sBf[2][1024];
    __shared__ __align__(16) unsigned sBg[2][1024];

    int tid = threadIdx.x;
    int am = tid >> 1, aks = tid & 1;
    int bn = tid >> 2, bkc = tid & 3;
    int ja = min(m0 + am, M - 1);
    int ca = g_idx[b * LC + ja];
    const float* Crow = C   + ((size_t)b * LC + ca) * DD;
    const float* Arow = g_A + ((size_t)b * LC + ja) * DD;
    const float* Bfrow = Wf + (size_t)(n0 + bn) * D4 + bkc * 8;
    const float* Bgrow = Wg + (size_t)(n0 + bn) * D4 + bkc * 8;

    int lane = tid & 31, w = tid >> 5;
    int wm = w >> 1, wn = w & 1;

    float accf[2][4][4], accg[2][4][4];
#pragma unroll
    for (int mi = 0; mi < 2; mi++)
#pragma unroll
        for (int ni = 0; ni < 4; ni++)
#pragma unroll
            for (int r = 0; r < 4; r++) { accf[mi][ni][r] = 0.f; accg[mi][ni][r] = 0.f; }

    unsigned ra[8], rbf[4], rbg[4];

#define LOAD_CAT(rr_, kg0_)                                                    \
    {                                                                          \
        int seg = (kg0_) >> 9;                                                 \
        int kk  = (kg0_) & 511;                                                \
        float4 cc[4], aa[4];                                                   \
        cc[0] = *(const float4*)(Crow + kk);                                   \
        cc[1] = *(const float4*)(Crow + kk + 4);                               \
        cc[2] = *(const float4*)(Crow + kk + 8);                               \
        cc[3] = *(const float4*)(Crow + kk + 12);                              \
        aa[0] = *(const float4*)(Arow + kk);                                   \
        aa[1] = *(const float4*)(Arow + kk + 4);                               \
        aa[2] = *(const float4*)(Arow + kk + 8);                               \
        aa[3] = *(const float4*)(Arow + kk + 12);                              \
        _Pragma("unroll")                                                      \
        for (int u = 0; u < 4; u++) {                                          \
            float4 cv = cc[u], av4 = aa[u], x;                                 \
            if (seg == 0)      x = cv;                                         \
            else if (seg == 1) x = av4;                                        \
            else if (seg == 2) x = make_float4(av4.x - cv.x, av4.y - cv.y,     \
                                               av4.z - cv.z, av4.w - cv.w);    \
            else               x = make_float4(av4.x * cv.x, av4.y * cv.y,     \
                                               av4.z * cv.z, av4.w * cv.w);    \
            (rr_)[u * 2 + 0] = pk(x.x, x.y);                                   \
            (rr_)[u * 2 + 1] = pk(x.z, x.w);                                   \
        }                                                                      \
    }

    LOAD_CAT(ra, aks * 16);
    loadB8(rbf, Bfrow);
    loadB8(rbg, Bgrow);

    const int KIT = D4 / 32;
    for (int it = 0; it < KIT; it++) {
        int buf = it & 1;
        stsA(sA[buf], am, aks, ra);
        stsB(sBf[buf], bn, bkc, rbf);
        stsB(sBg[buf], bn, bkc, rbg);
        __syncthreads();
        if (it + 1 < KIT) {
            LOAD_CAT(ra, (it + 1) * 32 + aks * 16);
            loadB8(rbf, Bfrow + (it + 1) * 32);
            loadB8(rbg, Bgrow + (it + 1) * 32);
        }
#pragma unroll
        for (int ks = 0; ks < 2; ks++) {
            uint4 av[2];
            uint2 bvf[4], bvg[4];
#pragma unroll
            for (int mi = 0; mi < 2; mi++)
                av[mi] = *(const uint4*)&sA[buf][(((wm * 2 + mi) * 2 + ks) * 32 + lane) * 4];
#pragma unroll
            for (int ni = 0; ni < 4; ni++) {
                bvf[ni] = *(const uint2*)&sBf[buf][(((wn * 4 + ni) * 2 + ks) * 32 + lane) * 2];
                bvg[ni] = *(const uint2*)&sBg[buf][(((wn * 4 + ni) * 2 + ks) * 32 + lane) * 2];
            }
#pragma unroll
            for (int mi = 0; mi < 2; mi++)
#pragma unroll
                for (int ni = 0; ni < 4; ni++) {
                    mma_bf16(accf[mi][ni], (const unsigned*)&av[mi], (const unsigned*)&bvf[ni]);
                    mma_bf16(accg[mi][ni], (const unsigned*)&av[mi], (const unsigned*)&bvg[ni]);
                }
        }
    }

    int gid = lane >> 2, tig = lane & 3;
    int segn = n0 >> 9;
#pragma unroll
    for (int mi = 0; mi < 2; mi++) {
#pragma unroll
        for (int rr = 0; rr < 2; rr++) {
            int jrow = m0 + wm * 32 + mi * 16 + gid + rr * 8;
            if (jrow < M) {
                int c = g_idx[b * LC + jrow];
                const float* crow = C   + ((size_t)b * LC + c) * DD;
                const float* arow = g_A + ((size_t)b * LC + jrow) * DD;
                float* orow = out + ((size_t)b * LC + c) * (size_t)D4;
#pragma unroll
                for (int ni = 0; ni < 4; ni++) {
#pragma unroll
                    for (int e = 0; e < 2; e++) {
                        int n = n0 + wn * 32 + ni * 8 + tig * 2 + e;
                        int nn = n & 511;
                        float cval = crow[nn];
                        float aval = arow[nn];
                        float catv = (segn == 0) ? cval
                                   : (segn == 1) ? aval
                                   : (segn == 2) ? (aval - cval)
                                                 : (aval * cval);
                        float df = accf[mi][ni][rr * 2 + e];
                        float dg = accg[mi][ni][rr * 2 + e];
                        float fv = tanhf(df + bfv[n]);
                        float gv = 1.0f / (1.0f + __expf(-(dg + bgv[n])));
                        orow[n] = gv * fv + (1.0f - gv) * catv;
                    }
                }
            }
        }
    }
}

extern "C" void kernel_launch(void* const* d_in, const int* in_sizes, int n_in,
                              void* d_out, int out_size) {
    const float* C     = (const float*)d_in[0];
    const float* Q     = (const float*)d_in[1];
    const int*   Cmask = (const int*)d_in[2];
    const int*   Qmask = (const int*)d_in[3];
    const float* W1    = (const float*)d_in[4];
    const float* b1    = (const float*)d_in[5];
    const float* Wf    = (const float*)d_in[6];
    const float* bfv   = (const float*)d_in[7];
    const float* Wg    = (const float*)d_in[8];
    const float* bgv   = (const float*)d_in[9];
    float* out = (float*)d_out;

    float* dCp; cudaGetSymbolAddress((void**)&dCp, g_Cp);
    float* dQp; cudaGetSymbolAddress((void**)&dQp, g_Qp);
    float* dS;  cudaGetSymbolAddress((void**)&dS,  g_S);
    float* dA;  cudaGetSymbolAddress((void**)&dA,  g_A);
    float* dQt; cudaGetSymbolAddress((void**)&dQt, g_Qt);

    compact_kernel<<<NB, 256>>>(Cmask);
    fill_masked_kernel<<<dim3(1, LC, NB), 128>>>(Cmask, out);
    transpose_q_kernel<<<dim3(DD / 32, LQ / 32, NB), dim3(32, 8)>>>(Q);

    // C_ = lrelu(C@W1^T + b1), compacted rows
    gemm_nt_mma<<<dim3(DD / 64, LC / 128, NB), 256>>>(
        C, DD, LC, W1, DD, 0, dCp, DD, b1, DD, LC, 1, 1, 0);
    // Q_ = lrelu(Q@W1^T + b1), all rows
    gemm_nt_mma<<<dim3(DD / 64, LQ / 128, NB), 256>>>(
        Q, DD, LQ, W1, DD, 0, dQp, DD, b1, DD, LQ, 0, 0, 0);
    // S = C_ @ Q_^T (compacted c; batched B = g_Qp)
    gemm_nt_mma<<<dim3(LQ / 64, LC / 128, NB), 256>>>(
        dCp, DD, LC, dQp, DD, LQ, dS, LQ, b1, DD, LC, 1, 0, 1);
    softmax_kernel<<<dim3(LC, NB), 256>>>(Qmask);
    // attn_C = S_ @ Qt^T (compacted c; batched B = g_Qt)
    gemm_nt_mma<<<dim3(DD / 64, LC / 128, NB), 256>>>(
        dS, LQ, LC, dQt, LQ, DD, dA, DD, b1, LQ, LC, 1, 0, 1);
    // out = gate*tanh(cat@Wf^T+bf) + (1-gate)*cat  (compacted c rows)
    final_mma<<<dim3(D4 / 64, LC / 128, NB), 256>>>(C, Wf, bfv, Wg, bgv, out);
}